// round 8
// baseline (speedup 1.0000x reference)
#include <cuda_runtime.h>
#include <cuda_fp16.h>
#include <cstdint>

#define BN_TOT 2048
#define M_DIM  256
#define CIN    64
#define CMID   256
#define COUT   256
#define W2P    320
#define AP     72          // fp16 smem pitch (144B rows), verified round 4

// device scratch (zero-alloc rule)
__device__ float  g_zmax[BN_TOT * CMID];   // 2 MB, final max(+bias)
__device__ __half g_w2bT[256 * 256];       // w2 cols 64..319 TRANSPOSED [d][o], fp16

// ---------------- PTX helpers ----------------
__device__ __forceinline__ unsigned smem_u32(const void* p) {
    return (unsigned)__cvta_generic_to_shared(p);
}
__device__ __forceinline__ void ldm4(unsigned r[4], unsigned addr) {
    asm volatile("ldmatrix.sync.aligned.m8n8.x4.shared.b16 {%0,%1,%2,%3}, [%4];"
                 : "=r"(r[0]), "=r"(r[1]), "=r"(r[2]), "=r"(r[3]) : "r"(addr));
}
__device__ __forceinline__ void mma_f16(float c[4], const unsigned a[4], const unsigned b[2]) {
    asm volatile("mma.sync.aligned.m16n8k16.row.col.f32.f16.f16.f32 "
                 "{%0,%1,%2,%3}, {%4,%5,%6,%7}, {%8,%9}, {%0,%1,%2,%3};"
                 : "+f"(c[0]), "+f"(c[1]), "+f"(c[2]), "+f"(c[3])
                 : "r"(a[0]), "r"(a[1]), "r"(a[2]), "r"(a[3]), "r"(b[0]), "r"(b[1]));
}

// ---------------------------------------------------------------------------
// Prep: w2b (cols 64..319) -> transposed fp16 [d][o] (tiny, once)
// ---------------------------------------------------------------------------
__global__ void prep_w2b(const float* __restrict__ w2) {
    int j = blockIdx.x * 256 + threadIdx.x;   // 0..65535
    int o = j & 255, d = j >> 8;              // write coalesced in o
    g_w2bT[d * 256 + o] = __float2half_rn(w2[(size_t)o * W2P + CIN + d]);
}

// ---------------------------------------------------------------------------
// Round-4 verified loader: 128 rows x 64 fp32 -> fp16 smem pitch AP
// ---------------------------------------------------------------------------
__device__ __forceinline__ void load_conv(__half* sm, const float* __restrict__ g,
                                          int row0, int pitch, int tid) {
#pragma unroll
    for (int it = 0; it < 4; it++) {
        int idx = it * 256 + tid;          // 0..1023
        int row = idx >> 3, q = idx & 7;
        const float* p = g + (size_t)(row0 + row) * pitch + q * 8;
        float4 v0 = *(const float4*)p;
        float4 v1 = *(const float4*)(p + 4);
        __half2 h0 = __halves2half2(__float2half_rn(v0.x), __float2half_rn(v0.y));
        __half2 h1 = __halves2half2(__float2half_rn(v0.z), __float2half_rn(v0.w));
        __half2 h2 = __halves2half2(__float2half_rn(v1.x), __float2half_rn(v1.y));
        __half2 h3 = __halves2half2(__float2half_rn(v1.z), __float2half_rn(v1.w));
        uint4 u;
        u.x = *(unsigned*)&h0; u.y = *(unsigned*)&h1;
        u.z = *(unsigned*)&h2; u.w = *(unsigned*)&h3;
        *(uint4*)(sm + row * AP + q * 8) = u;
    }
}

// ---------------------------------------------------------------------------
// Round-4 verified MMA core: 128x128x64, warp tile 32m x 64n
// ---------------------------------------------------------------------------
__device__ __forceinline__ void mma_core(float acc[2][8][4],
                                         const __half* sA, const __half* sB,
                                         int warp_m, int warp_n, int lane) {
    const int lrow = lane & 15, lkh = (lane >> 4) * 8;
#pragma unroll
    for (int ks = 0; ks < 64; ks += 16) {
        unsigned af[2][4];
#pragma unroll
        for (int mi = 0; mi < 2; mi++)
            ldm4(af[mi], smem_u32(sA + (warp_m * 32 + mi * 16 + lrow) * AP + ks + lkh));
        unsigned bf[8][2];
#pragma unroll
        for (int np = 0; np < 4; np++) {
            unsigned t[4];
            ldm4(t, smem_u32(sB + (warp_n * 64 + np * 16 + lrow) * AP + ks + lkh));
            bf[2*np][0]   = t[0]; bf[2*np+1][0] = t[1];
            bf[2*np][1]   = t[2]; bf[2*np+1][1] = t[3];
        }
#pragma unroll
        for (int mi = 0; mi < 2; mi++)
#pragma unroll
            for (int ni = 0; ni < 8; ni++)
                mma_f16(acc[mi][ni], af[mi], bf[ni]);
    }
}

// ---------------------------------------------------------------------------
// K1 (exact round-4 shape): grid(2 dt, BN). z = x @ w1^T, max over 256 m,
// + bias -> g_zmax
// ---------------------------------------------------------------------------
__global__ void __launch_bounds__(256)
k1_mma_max(const float* __restrict__ x, const float* __restrict__ w1,
           const float* __restrict__ b1)
{
    __shared__ __align__(16) __half sA[128 * AP];
    __shared__ __align__(16) __half sB[128 * AP];
    __shared__ float smax[4][128];

    const int tid = threadIdx.x;
    const int lane = tid & 31, w = tid >> 5;
    const int warp_m = w >> 1, warp_n = w & 1;
    const int dt = blockIdx.x, bn = blockIdx.y;

    smax[tid >> 7][tid & 127] = -3.4e38f;
    smax[2 + (tid >> 7)][tid & 127] = -3.4e38f;

    load_conv(sB, w1, dt * 128, CIN, tid);

#pragma unroll
    for (int mt = 0; mt < 2; mt++) {
        __syncthreads();
        load_conv(sA, x, bn * 256 + mt * 128, CIN, tid);
        __syncthreads();

        float acc[2][8][4];
#pragma unroll
        for (int mi = 0; mi < 2; mi++)
#pragma unroll
            for (int ni = 0; ni < 8; ni++)
#pragma unroll
                for (int c = 0; c < 4; c++) acc[mi][ni][c] = 0.f;

        mma_core(acc, sA, sB, warp_m, warp_n, lane);

#pragma unroll
        for (int ni = 0; ni < 8; ni++) {
            float m0 = fmaxf(fmaxf(acc[0][ni][0], acc[0][ni][2]),
                             fmaxf(acc[1][ni][0], acc[1][ni][2]));
            float m1 = fmaxf(fmaxf(acc[0][ni][1], acc[0][ni][3]),
                             fmaxf(acc[1][ni][1], acc[1][ni][3]));
#pragma unroll
            for (int off = 4; off < 32; off <<= 1) {
                m0 = fmaxf(m0, __shfl_xor_sync(0xffffffffu, m0, off));
                m1 = fmaxf(m1, __shfl_xor_sync(0xffffffffu, m1, off));
            }
            if (lane < 4) {
                int col = warp_n * 64 + ni * 8 + lane * 2;
                smax[warp_m][col]     = fmaxf(smax[warp_m][col], m0);
                smax[warp_m][col + 1] = fmaxf(smax[warp_m][col + 1], m1);
            }
        }
    }

    __syncthreads();
    if (tid < 128) {
        float m = fmaxf(fmaxf(smax[0][tid], smax[1][tid]),
                        fmaxf(smax[2][tid], smax[3][tid]));
        g_zmax[(size_t)bn * CMID + dt * 128 + tid] = m + b1[dt * 128 + tid];
    }
}

// ---------------------------------------------------------------------------
// K3 (round-4 shape + folded v): grid(2 nt, BN). v-slice prologue, then
// out = x @ w2a^T + v, 2 row phases.
// ---------------------------------------------------------------------------
__global__ void __launch_bounds__(256)
k3_mma_out(const float* __restrict__ x, const float* __restrict__ w2,
           float* __restrict__ out)
{
    __shared__ __align__(16) __half sA[128 * AP];
    __shared__ __align__(16) __half sB[128 * AP];
    __shared__ float svp[256];
    __shared__ float sv[128];

    const int tid = threadIdx.x;
    const int lane = tid & 31, w = tid >> 5;
    const int warp_m = w >> 1, warp_n = w & 1;
    const int nt = blockIdx.x, bn = blockIdx.y;

    load_conv(sB, w2, nt * 128, W2P, tid);   // w2a = first 64 cols of pitch-320 rows

    // v-slice: thread t -> output o = nt*128 + (t&127), k-half = t>>7
    {
        const int o = tid & 127, kh = tid >> 7;
        const float* zm = g_zmax + (size_t)bn * CMID + kh * 128;
        const __half* wb = g_w2bT + (size_t)(kh * 128) * 256 + nt * 128 + o;
        float acc = 0.f;
#pragma unroll 8
        for (int k = 0; k < 128; k++)
            acc = fmaf(zm[k], __half2float(wb[(size_t)k * 256]), acc);
        svp[tid] = acc;
    }
    __syncthreads();
    if (tid < 128) sv[tid] = svp[tid] + svp[tid + 128];

#pragma unroll
    for (int rt = 0; rt < 2; rt++) {
        const int r0 = bn * 256 + rt * 128;
        __syncthreads();
        load_conv(sA, x, r0, CIN, tid);
        __syncthreads();

        float acc[2][8][4];
#pragma unroll
        for (int mi = 0; mi < 2; mi++)
#pragma unroll
            for (int ni = 0; ni < 8; ni++)
#pragma unroll
                for (int c = 0; c < 4; c++) acc[mi][ni][c] = 0.f;

        mma_core(acc, sA, sB, warp_m, warp_n, lane);

#pragma unroll
        for (int ni = 0; ni < 8; ni++) {
            int cfrag = warp_n * 64 + ni * 8 + (lane & 3) * 2;
            int col = nt * 128 + cfrag;
            float2 vv = *(const float2*)(sv + cfrag);
#pragma unroll
            for (int mi = 0; mi < 2; mi++) {
                int row = r0 + warp_m * 32 + mi * 16 + (lane >> 2);
                float2 o0v, o1v;
                o0v.x = acc[mi][ni][0] + vv.x; o0v.y = acc[mi][ni][1] + vv.y;
                o1v.x = acc[mi][ni][2] + vv.x; o1v.y = acc[mi][ni][3] + vv.y;
                *(float2*)(out + (size_t)row * COUT + col)       = o0v;
                *(float2*)(out + (size_t)(row + 8) * COUT + col) = o1v;
            }
        }
    }
}

// ---------------------------------------------------------------------------
extern "C" void kernel_launch(void* const* d_in, const int* in_sizes, int n_in,
                              void* d_out, int out_size) {
    const float* x  = (const float*)d_in[0];   // (8,256,256,64)
    const float* w1 = (const float*)d_in[1];   // (256,64)
    const float* b1 = (const float*)d_in[2];   // (256,)
    const float* w2 = (const float*)d_in[3];   // (256,320)
    float* out = (float*)d_out;                // (8,256,256,256)

    prep_w2b<<<256, 256>>>(w2);

    dim3 g1(2, BN_TOT);
    k1_mma_max<<<g1, 256>>>(x, w1, b1);

    dim3 g3(2, BN_TOT);
    k3_mma_out<<<g3, 256>>>(x, w2, out);
}

// round 9
// speedup vs baseline: 1.1782x; 1.1782x over previous
#include <cuda_runtime.h>
#include <cuda_fp16.h>
#include <cstdint>

#define BN_TOT 2048
#define M_DIM  256
#define CIN    64
#define CMID   256
#define COUT   256
#define W2P    320
#define AP     72          // fp16 smem pitch (144B rows), verified round 4

// device scratch (zero-alloc rule)
__device__ float  g_zmax[BN_TOT * CMID];   // 2 MB, final max(+bias)
__device__ float  g_v[BN_TOT * COUT];      // 2 MB
__device__ __half g_w2bT[256 * 256];       // w2 cols 64..319 TRANSPOSED [d][o], fp16

// ---------------- PTX helpers ----------------
__device__ __forceinline__ unsigned smem_u32(const void* p) {
    return (unsigned)__cvta_generic_to_shared(p);
}
__device__ __forceinline__ void ldm4(unsigned r[4], unsigned addr) {
    asm volatile("ldmatrix.sync.aligned.m8n8.x4.shared.b16 {%0,%1,%2,%3}, [%4];"
                 : "=r"(r[0]), "=r"(r[1]), "=r"(r[2]), "=r"(r[3]) : "r"(addr));
}
__device__ __forceinline__ void mma_f16(float c[4], const unsigned a[4], const unsigned b[2]) {
    asm volatile("mma.sync.aligned.m16n8k16.row.col.f32.f16.f16.f32 "
                 "{%0,%1,%2,%3}, {%4,%5,%6,%7}, {%8,%9}, {%0,%1,%2,%3};"
                 : "+f"(c[0]), "+f"(c[1]), "+f"(c[2]), "+f"(c[3])
                 : "r"(a[0]), "r"(a[1]), "r"(a[2]), "r"(a[3]), "r"(b[0]), "r"(b[1]));
}

// ---------------------------------------------------------------------------
// Prep: w2b (cols 64..319) -> transposed fp16 [d][o] (tiny, once)
// ---------------------------------------------------------------------------
__global__ void prep_w2b(const float* __restrict__ w2) {
    int j = blockIdx.x * 256 + threadIdx.x;   // 0..65535
    int o = j & 255, d = j >> 8;              // write coalesced in o
    g_w2bT[d * 256 + o] = __float2half_rn(w2[(size_t)o * W2P + CIN + d]);
}

// ---------------------------------------------------------------------------
// Round-4 verified loader: 128 rows x 64 fp32 -> fp16 smem pitch AP
// ---------------------------------------------------------------------------
__device__ __forceinline__ void load_conv(__half* sm, const float* __restrict__ g,
                                          int row0, int pitch, int tid) {
#pragma unroll
    for (int it = 0; it < 4; it++) {
        int idx = it * 256 + tid;          // 0..1023
        int row = idx >> 3, q = idx & 7;
        const float* p = g + (size_t)(row0 + row) * pitch + q * 8;
        float4 v0 = *(const float4*)p;
        float4 v1 = *(const float4*)(p + 4);
        __half2 h0 = __halves2half2(__float2half_rn(v0.x), __float2half_rn(v0.y));
        __half2 h1 = __halves2half2(__float2half_rn(v0.z), __float2half_rn(v0.w));
        __half2 h2 = __halves2half2(__float2half_rn(v1.x), __float2half_rn(v1.y));
        __half2 h3 = __halves2half2(__float2half_rn(v1.z), __float2half_rn(v1.w));
        uint4 u;
        u.x = *(unsigned*)&h0; u.y = *(unsigned*)&h1;
        u.z = *(unsigned*)&h2; u.w = *(unsigned*)&h3;
        *(uint4*)(sm + row * AP + q * 8) = u;
    }
}

// ---------------------------------------------------------------------------
// Round-4 verified MMA core: 128x128x64, warp tile 32m x 64n
// ---------------------------------------------------------------------------
__device__ __forceinline__ void mma_core(float acc[2][8][4],
                                         const __half* sA, const __half* sB,
                                         int warp_m, int warp_n, int lane) {
    const int lrow = lane & 15, lkh = (lane >> 4) * 8;
#pragma unroll
    for (int ks = 0; ks < 64; ks += 16) {
        unsigned af[2][4];
#pragma unroll
        for (int mi = 0; mi < 2; mi++)
            ldm4(af[mi], smem_u32(sA + (warp_m * 32 + mi * 16 + lrow) * AP + ks + lkh));
        unsigned bf[8][2];
#pragma unroll
        for (int np = 0; np < 4; np++) {
            unsigned t[4];
            ldm4(t, smem_u32(sB + (warp_n * 64 + np * 16 + lrow) * AP + ks + lkh));
            bf[2*np][0]   = t[0]; bf[2*np+1][0] = t[1];
            bf[2*np][1]   = t[2]; bf[2*np+1][1] = t[3];
        }
#pragma unroll
        for (int mi = 0; mi < 2; mi++)
#pragma unroll
            for (int ni = 0; ni < 8; ni++)
                mma_f16(acc[mi][ni], af[mi], bf[ni]);
    }
}

// ---------------------------------------------------------------------------
// K1 (round-4 shape, +minBlocks 3): grid(2 dt, BN). z = x @ w1^T,
// max over 256 m, + bias -> g_zmax
// ---------------------------------------------------------------------------
__global__ void __launch_bounds__(256, 3)
k1_mma_max(const float* __restrict__ x, const float* __restrict__ w1,
           const float* __restrict__ b1)
{
    __shared__ __align__(16) __half sA[128 * AP];
    __shared__ __align__(16) __half sB[128 * AP];
    __shared__ float smax[4][128];

    const int tid = threadIdx.x;
    const int lane = tid & 31, w = tid >> 5;
    const int warp_m = w >> 1, warp_n = w & 1;
    const int dt = blockIdx.x, bn = blockIdx.y;

    smax[tid >> 7][tid & 127] = -3.4e38f;
    smax[2 + (tid >> 7)][tid & 127] = -3.4e38f;

    load_conv(sB, w1, dt * 128, CIN, tid);

#pragma unroll
    for (int mt = 0; mt < 2; mt++) {
        __syncthreads();
        load_conv(sA, x, bn * 256 + mt * 128, CIN, tid);
        __syncthreads();

        float acc[2][8][4];
#pragma unroll
        for (int mi = 0; mi < 2; mi++)
#pragma unroll
            for (int ni = 0; ni < 8; ni++)
#pragma unroll
                for (int c = 0; c < 4; c++) acc[mi][ni][c] = 0.f;

        mma_core(acc, sA, sB, warp_m, warp_n, lane);

#pragma unroll
        for (int ni = 0; ni < 8; ni++) {
            float m0 = fmaxf(fmaxf(acc[0][ni][0], acc[0][ni][2]),
                             fmaxf(acc[1][ni][0], acc[1][ni][2]));
            float m1 = fmaxf(fmaxf(acc[0][ni][1], acc[0][ni][3]),
                             fmaxf(acc[1][ni][1], acc[1][ni][3]));
#pragma unroll
            for (int off = 4; off < 32; off <<= 1) {
                m0 = fmaxf(m0, __shfl_xor_sync(0xffffffffu, m0, off));
                m1 = fmaxf(m1, __shfl_xor_sync(0xffffffffu, m1, off));
            }
            if (lane < 4) {
                int col = warp_n * 64 + ni * 8 + lane * 2;
                smax[warp_m][col]     = fmaxf(smax[warp_m][col], m0);
                smax[warp_m][col + 1] = fmaxf(smax[warp_m][col + 1], m1);
            }
        }
    }

    __syncthreads();
    if (tid < 128) {
        float m = fmaxf(fmaxf(smax[0][tid], smax[1][tid]),
                        fmaxf(smax[2][tid], smax[3][tid]));
        g_zmax[(size_t)bn * CMID + dt * 128 + tid] = m + b1[dt * 128 + tid];
    }
}

// ---------------------------------------------------------------------------
// K2 (new): grid(BN_TOT/4). Each CTA: 4 bn rows x all 256 outputs.
// thread = o; w2bT [d][o] coalesced; zmax rows in smem; 4 acc chains.
// ---------------------------------------------------------------------------
__global__ void __launch_bounds__(256)
k2_v()
{
    __shared__ float zs[4][256];
    const int tid = threadIdx.x;
    const int bn0 = blockIdx.x * 4;

#pragma unroll
    for (int i = 0; i < 4; i++)
        zs[i][tid] = g_zmax[(size_t)(bn0 + i) * CMID + tid];
    __syncthreads();

    float a0 = 0.f, a1 = 0.f, a2 = 0.f, a3 = 0.f;
    const __half* wp = g_w2bT + tid;
#pragma unroll 4
    for (int d = 0; d < 256; d += 2) {
        float w0 = __half2float(wp[(size_t)d * 256]);
        float w1v = __half2float(wp[(size_t)(d + 1) * 256]);
        float2 z0 = *(const float2*)&zs[0][d];
        float2 z1 = *(const float2*)&zs[1][d];
        float2 z2 = *(const float2*)&zs[2][d];
        float2 z3 = *(const float2*)&zs[3][d];
        a0 = fmaf(z0.x, w0, a0); a0 = fmaf(z0.y, w1v, a0);
        a1 = fmaf(z1.x, w0, a1); a1 = fmaf(z1.y, w1v, a1);
        a2 = fmaf(z2.x, w0, a2); a2 = fmaf(z2.y, w1v, a2);
        a3 = fmaf(z3.x, w0, a3); a3 = fmaf(z3.y, w1v, a3);
    }
    g_v[(size_t)(bn0 + 0) * COUT + tid] = a0;
    g_v[(size_t)(bn0 + 1) * COUT + tid] = a1;
    g_v[(size_t)(bn0 + 2) * COUT + tid] = a2;
    g_v[(size_t)(bn0 + 3) * COUT + tid] = a3;
}

// ---------------------------------------------------------------------------
// K3 (exact round-4): grid(2 nt, BN). out = x @ w2a^T + v, 2 row phases.
// ---------------------------------------------------------------------------
__global__ void __launch_bounds__(256)
k3_mma_out(const float* __restrict__ x, const float* __restrict__ w2,
           float* __restrict__ out)
{
    __shared__ __align__(16) __half sA[128 * AP];
    __shared__ __align__(16) __half sB[128 * AP];
    __shared__ float sv[128];

    const int tid = threadIdx.x;
    const int lane = tid & 31, w = tid >> 5;
    const int warp_m = w >> 1, warp_n = w & 1;
    const int nt = blockIdx.x, bn = blockIdx.y;

    if (tid < 128) sv[tid] = g_v[(size_t)bn * COUT + nt * 128 + tid];

    load_conv(sB, w2, nt * 128, W2P, tid);   // w2a = first 64 cols of pitch-320 rows

#pragma unroll
    for (int rt = 0; rt < 2; rt++) {
        const int r0 = bn * 256 + rt * 128;
        __syncthreads();
        load_conv(sA, x, r0, CIN, tid);
        __syncthreads();

        float acc[2][8][4];
#pragma unroll
        for (int mi = 0; mi < 2; mi++)
#pragma unroll
            for (int ni = 0; ni < 8; ni++)
#pragma unroll
                for (int c = 0; c < 4; c++) acc[mi][ni][c] = 0.f;

        mma_core(acc, sA, sB, warp_m, warp_n, lane);

#pragma unroll
        for (int ni = 0; ni < 8; ni++) {
            int cfrag = warp_n * 64 + ni * 8 + (lane & 3) * 2;
            int col = nt * 128 + cfrag;
            float2 vv = *(const float2*)(sv + cfrag);
#pragma unroll
            for (int mi = 0; mi < 2; mi++) {
                int row = r0 + warp_m * 32 + mi * 16 + (lane >> 2);
                float2 o0v, o1v;
                o0v.x = acc[mi][ni][0] + vv.x; o0v.y = acc[mi][ni][1] + vv.y;
                o1v.x = acc[mi][ni][2] + vv.x; o1v.y = acc[mi][ni][3] + vv.y;
                *(float2*)(out + (size_t)row * COUT + col)       = o0v;
                *(float2*)(out + (size_t)(row + 8) * COUT + col) = o1v;
            }
        }
    }
}

// ---------------------------------------------------------------------------
extern "C" void kernel_launch(void* const* d_in, const int* in_sizes, int n_in,
                              void* d_out, int out_size) {
    const float* x  = (const float*)d_in[0];   // (8,256,256,64)
    const float* w1 = (const float*)d_in[1];   // (256,64)
    const float* b1 = (const float*)d_in[2];   // (256,)
    const float* w2 = (const float*)d_in[3];   // (256,320)
    float* out = (float*)d_out;                // (8,256,256,256)

    prep_w2b<<<256, 256>>>(w2);

    dim3 g1(2, BN_TOT);
    k1_mma_max<<<g1, 256>>>(x, w1, b1);

    k2_v<<<BN_TOT / 4, 256>>>();

    dim3 g3(2, BN_TOT);
    k3_mma_out<<<g3, 256>>>(x, w2, out);
}